// round 16
// baseline (speedup 1.0000x reference)
#include <cuda_runtime.h>
#include <cuda_bf16.h>
#include <cuda_fp16.h>
#include <math.h>
#include <stdint.h>

// Problem constants
#define N_TOK 2048
#define HDIM  2048
#define IDIM  1408
#define NEXP  64
#define NGRP  8
#define GSZ   8
#define TOPK  8

// GEMM tiling (fp16 operands in smem)
#define KC      64
#define ROWB    144
#define TILE_SZ (128*ROWB)
#define STAGE_SZ (2*TILE_SZ)
#define NSTAGE  3
#define SMEM_TOTAL (NSTAGE*STAGE_SZ)  // 110592 B
#define NC1 (HDIM/KC)                 // 32
#define NC2 (IDIM/KC)                 // 22

#define RT_TOK 8
#define RT_SMEM (RT_TOK*HDIM*4)       // 65536 B dynamic smem for route
#define PP_SMEM (HDIM*9*4)            // 73728 B dynamic smem for pproj (stride-9 M)

// ---------------------------------------------------------------------------
// Device global scratch
// ---------------------------------------------------------------------------
__device__ float g_soft[(size_t)N_TOK * NGRP * GSZ];
__device__ float g_scalar[(size_t)N_TOK * NGRP];
__device__ float g_Pg[(size_t)NGRP * IDIM * GSZ];
__device__ float g_Pu[(size_t)NGRP * IDIM * GSZ];

__device__ int g_list[NGRP][N_TOK];
__device__ int g_cnt[NGRP];

__device__ __half g_xf[(size_t)N_TOK * HDIM];
__device__ __half g_wgf[(size_t)NGRP * IDIM * HDIM];
__device__ __half g_wuf[(size_t)NGRP * IDIM * HDIM];
__device__ __half g_wdf[(size_t)NGRP * HDIM * IDIM];
__device__ __half g_actf[(size_t)NGRP * N_TOK * IDIM];

// ---------------------------------------------------------------------------
// PTX helpers (sm_80-portable only)
// ---------------------------------------------------------------------------
__device__ __forceinline__ uint32_t s2u(const void* p) {
    uint32_t a;
    asm("{ .reg .u64 t; cvta.to.shared.u64 t, %1; cvt.u32.u64 %0, t; }"
        : "=r"(a) : "l"(p));
    return a;
}
__device__ __forceinline__ void cpasync16(uint32_t s, const void* g) {
    asm volatile("cp.async.cg.shared.global [%0], [%1], 16;"
                 :: "r"(s), "l"(g) : "memory");
}
#define CP_COMMIT() asm volatile("cp.async.commit_group;" ::: "memory")
#define CP_WAIT(n)  asm volatile("cp.async.wait_group %0;" :: "n"(n) : "memory")

__device__ __forceinline__ void ldsm4(uint32_t* r, uint32_t addr) {
    asm volatile("ldmatrix.sync.aligned.m8n8.x4.shared.b16 {%0,%1,%2,%3}, [%4];"
                 : "=r"(r[0]), "=r"(r[1]), "=r"(r[2]), "=r"(r[3]) : "r"(addr));
}
__device__ __forceinline__ void mma16816(float* d, const uint32_t* a,
                                         uint32_t b0, uint32_t b1) {
    asm volatile(
        "mma.sync.aligned.m16n8k16.row.col.f32.f16.f16.f32 "
        "{%0,%1,%2,%3}, {%4,%5,%6,%7}, {%8,%9}, {%0,%1,%2,%3};"
        : "+f"(d[0]), "+f"(d[1]), "+f"(d[2]), "+f"(d[3])
        : "r"(a[0]), "r"(a[1]), "r"(a[2]), "r"(a[3]), "r"(b0), "r"(b1));
}

// ---------------------------------------------------------------------------
// Prep: fp32 -> fp16 (only Wd)
// ---------------------------------------------------------------------------
__global__ __launch_bounds__(256) void to_half(
    const float4* __restrict__ src, uint2* __restrict__ dst, int n4)
{
    for (int i = blockIdx.x * 256 + threadIdx.x; i < n4; i += gridDim.x * 256) {
        float4 v = src[i];
        __half2 a = __floats2half2_rn(v.x, v.y);
        __half2 b = __floats2half2_rn(v.z, v.w);
        uint2 o;
        o.x = *(uint32_t*)&a;
        o.y = *(uint32_t*)&b;
        dst[i] = o;
    }
}

// ---------------------------------------------------------------------------
// Routing: 8 tokens/block (gate_w reuse x8), fused x->fp16,
// warp-per-token softmax/top-8 (lower-index tie-break = first-wins).
// ---------------------------------------------------------------------------
__global__ __launch_bounds__(256) void moe_route(
    const float* __restrict__ x, const float* __restrict__ gate_w,
    const void* __restrict__ inv_map_raw)
{
    extern __shared__ float xs[];            // RT_TOK * HDIM
    __shared__ float sc[RT_TOK][NEXP];

    const int tid = threadIdx.x;
    const int n0 = blockIdx.x * RT_TOK;
    const int warp = tid >> 5, lane = tid & 31;

    for (int u = tid; u < RT_TOK * HDIM / 4; u += 256) {
        const int row = u >> 9;
        const int c4 = u & 511;
        float4 v = ((const float4*)(x + (size_t)(n0 + row) * HDIM))[c4];
        ((float4*)(xs + row * HDIM))[c4] = v;
        __half2 h0 = __floats2half2_rn(v.x, v.y);
        __half2 h1 = __floats2half2_rn(v.z, v.w);
        uint2 o; o.x = *(uint32_t*)&h0; o.y = *(uint32_t*)&h1;
        ((uint2*)(g_xf + (size_t)(n0 + row) * HDIM))[c4] = o;
    }
    __syncthreads();

    float acc[RT_TOK][8];
#pragma unroll
    for (int t = 0; t < RT_TOK; t++)
#pragma unroll
        for (int j = 0; j < 8; j++) acc[t][j] = 0.f;

    const float* gw = gate_w + (size_t)(warp * 8) * HDIM;
    for (int h = lane; h < HDIM; h += 32) {
        float gv[8];
#pragma unroll
        for (int j = 0; j < 8; j++) gv[j] = gw[(size_t)j * HDIM + h];
#pragma unroll
        for (int t = 0; t < RT_TOK; t++) {
            const float xv = xs[t * HDIM + h];
#pragma unroll
            for (int j = 0; j < 8; j++) acc[t][j] += xv * gv[j];
        }
    }
#pragma unroll
    for (int t = 0; t < RT_TOK; t++)
#pragma unroll
        for (int j = 0; j < 8; j++) {
            float v = acc[t][j];
#pragma unroll
            for (int o = 16; o > 0; o >>= 1)
                v += __shfl_down_sync(0xffffffffu, v, o);
            if (lane == 0) sc[t][warp * 8 + j] = v;
        }
    __syncthreads();

    {
        const int t = warp;
        const int n = n0 + t;
        float v0 = sc[t][lane], v1 = sc[t][lane + 32];

        float m = fmaxf(v0, v1);
#pragma unroll
        for (int o = 16; o > 0; o >>= 1)
            m = fmaxf(m, __shfl_xor_sync(0xffffffffu, m, o));
        float e0 = expf(v0 - m), e1 = expf(v1 - m);
        float s = e0 + e1;
#pragma unroll
        for (int o = 16; o > 0; o >>= 1)
            s += __shfl_xor_sync(0xffffffffu, s, o);
        const float inv = 1.f / s;
        float a0 = e0 * inv, a1 = e1 * inv;

        float win_val[TOPK]; int win_idx[TOPK];
#pragma unroll
        for (int k = 0; k < TOPK; k++) {
            float bv; int bi;
            if (a0 >= a1) { bv = a0; bi = lane; } else { bv = a1; bi = lane + 32; }
#pragma unroll
            for (int o = 16; o > 0; o >>= 1) {
                float ov = __shfl_xor_sync(0xffffffffu, bv, o);
                int   oi = __shfl_xor_sync(0xffffffffu, bi, o);
                if (ov > bv || (ov == bv && oi < bi)) { bv = ov; bi = oi; }
            }
            win_val[k] = bv; win_idx[k] = bi;
            if (bi == lane)      a0 = -1.f;
            if (bi == lane + 32) a1 = -1.f;
        }

        if (lane < NGRP) {
            const int g = lane;
            const int* im32 = (const int*)inv_map_raw;
            const bool is64 = (im32[1] == 0);
            const long long* im64 = (const long long*)inv_map_raw;
            float f[GSZ]; float ss = 0.f;
#pragma unroll
            for (int sl = 0; sl < GSZ; sl++) {
                const int slot = g * GSZ + sl;
                const int e = is64 ? (int)im64[slot] : im32[slot];
                float w = 0.f;
#pragma unroll
                for (int k = 0; k < TOPK; k++)
                    if (win_idx[k] == e) w = win_val[k];
                f[sl] = w; ss += w;
            }
            g_scalar[(size_t)n * NGRP + g] = ss;
            float mx = -1e30f;
#pragma unroll
            for (int sl = 0; sl < GSZ; sl++) {
                float v = (f[sl] == 0.f) ? -1e9f : f[sl];
                f[sl] = v; mx = fmaxf(mx, v);
            }
            float es = 0.f;
#pragma unroll
            for (int sl = 0; sl < GSZ; sl++) { float v = expf(f[sl] - mx); f[sl] = v; es += v; }
            const float iv = 1.f / es;
#pragma unroll
            for (int sl = 0; sl < GSZ; sl++)
                g_soft[((size_t)n * NGRP + g) * GSZ + sl] = f[sl] * iv;
        }
    }
}

// ---------------------------------------------------------------------------
// Compaction
// ---------------------------------------------------------------------------
__global__ __launch_bounds__(256) void moe_compact()
{
    const int g = blockIdx.x, tid = threadIdx.x;
    __shared__ int warpsum[8];

    int flags[8]; int local = 0;
#pragma unroll
    for (int j = 0; j < 8; j++) {
        const int t = tid * 8 + j;
        flags[j] = (g_scalar[(size_t)t * NGRP + g] != 0.f) ? 1 : 0;
        local += flags[j];
    }
    int v = local;
#pragma unroll
    for (int o = 1; o < 32; o <<= 1) {
        int nv = __shfl_up_sync(0xffffffffu, v, o);
        if ((tid & 31) >= o) v += nv;
    }
    if ((tid & 31) == 31) warpsum[tid >> 5] = v;
    __syncthreads();
    if (tid < 8) {
        int w = warpsum[tid];
#pragma unroll
        for (int o = 1; o < 8; o <<= 1) {
            int nw = __shfl_up_sync(0xffu, w, o);
            if (tid >= o) w += nw;
        }
        warpsum[tid] = w;
    }
    __syncthreads();
    int base = v - local + ((tid >= 32) ? warpsum[(tid >> 5) - 1] : 0);
#pragma unroll
    for (int j = 0; j < 8; j++) {
        if (flags[j]) g_list[g][base++] = tid * 8 + j;
    }
    if (tid == 255) g_cnt[g] = base;
}

// ---------------------------------------------------------------------------
// P projections (fp32 exact): M_g staged in smem (stride 9, conflict-free),
// fused Wg/Wu -> fp16. One block = 8 rows (i) of ONE group (IDIM/8=176 | grid).
// ---------------------------------------------------------------------------
__global__ __launch_bounds__(256) void moe_pproj(
    const float* __restrict__ Wg, const float* __restrict__ Wu,
    const float* __restrict__ M)
{
    extern __shared__ float ms[];            // HDIM rows x stride 9
    const int tid = threadIdx.x;
    const int b = blockIdx.x;
    const int g = b / (IDIM / 8);
    const int i0 = (b % (IDIM / 8)) * 8;
    const int warp = tid >> 5, lane = tid & 31;

    // stage M_g: HDIM x 8 floats -> stride-9 smem rows
    {
        const float4* m4 = (const float4*)(M + (size_t)g * HDIM * GSZ);
        for (int u = tid; u < HDIM * 2; u += 256) {
            const int row = u >> 1, hf = u & 1;
            float4 v = m4[u];
            float* d = ms + row * 9 + hf * 4;
            d[0] = v.x; d[1] = v.y; d[2] = v.z; d[3] = v.w;
        }
    }
    __syncthreads();

    const int i = i0 + warp;
    const size_t rowoff = ((size_t)g * IDIM + i) * HDIM;
    const float* wgr = Wg + rowoff;
    const float* wur = Wu + rowoff;
    __half* wgo = g_wgf + rowoff;
    __half* wuo = g_wuf + rowoff;

    float ag[8], au[8];
#pragma unroll
    for (int s = 0; s < 8; s++) { ag[s] = 0.f; au[s] = 0.f; }

    for (int h = lane; h < HDIM; h += 32) {
        const float wgv = wgr[h];
        const float wuv = wur[h];
        wgo[h] = __float2half_rn(wgv);
        wuo[h] = __float2half_rn(wuv);
        const float* mr = ms + h * 9;        // stride 9 -> conflict-free
#pragma unroll
        for (int s = 0; s < 8; s++) {
            ag[s] += wgv * mr[s];
            au[s] += wuv * mr[s];
        }
    }
#pragma unroll
    for (int s = 0; s < 8; s++) {
#pragma unroll
        for (int o = 16; o > 0; o >>= 1) {
            ag[s] += __shfl_down_sync(0xffffffffu, ag[s], o);
            au[s] += __shfl_down_sync(0xffffffffu, au[s], o);
        }
    }
    if (lane == 0) {
        float* pg = &g_Pg[((size_t)g * IDIM + i) * GSZ];
        float* pu = &g_Pu[((size_t)g * IDIM + i) * GSZ];
#pragma unroll
        for (int s = 0; s < 8; s++) { pg[s] = ag[s]; pu[s] = au[s]; }
    }
}

// ---------------------------------------------------------------------------
// fp16 warp-MMA stage: warp tile 64(m) x 32(n), KC=64.
// ---------------------------------------------------------------------------
__device__ __forceinline__ void mma_stage(uint32_t sbuf, int wm, int wn, int lane,
                                          float acc[4][4][4]) {
    const uint32_t lm = (uint32_t)((lane & 15) * ROWB + (lane >> 4) * 16);
#pragma unroll
    for (int s = 0; s < 4; s++) {
        const uint32_t base = sbuf + lm + s * 32;
        uint32_t a[4][4], bx[2][4];
#pragma unroll
        for (int mt = 0; mt < 4; mt++)
            ldsm4(a[mt], base + (wm * 64 + mt * 16) * ROWB);
#pragma unroll
        for (int bt = 0; bt < 2; bt++)
            ldsm4(bx[bt], base + TILE_SZ + (wn * 32 + bt * 16) * ROWB);
#pragma unroll
        for (int mt = 0; mt < 4; mt++)
#pragma unroll
            for (int j = 0; j < 4; j++)
                mma16816(acc[mt][j], a[mt],
                         bx[j >> 1][j & 1], bx[j >> 1][2 + (j & 1)]);
    }
}

// ---------------------------------------------------------------------------
// G1 (compacted): act_c[g, pos0..+128, i0..+64]; 3-stage ring, 1 sync/chunk.
// ---------------------------------------------------------------------------
__global__ __launch_bounds__(256, 2) void moe_g1_mma()
{
    extern __shared__ char smem[];
    const uint32_t sb = s2u(smem);
    const int tid = threadIdx.x, lane = tid & 31;
    const int wn = (tid >> 5) & 3, wm = tid >> 7;
    const int g = blockIdx.z, i0 = blockIdx.y * 64, n0 = blockIdx.x * 128;

    const int cnt = g_cnt[g];
    if (n0 >= cnt) return;

    const __half* srcs[8];
    uint32_t dsts[8];
#pragma unroll
    for (int i = 0; i < 8; i++) {
        const int id = tid + i * 256;
        const int tile = id >> 10, rr = (id >> 3) & 127, cc = id & 7;
        const __half* p;
        if (tile == 0) {
            const int j = n0 + rr;
            const int t = g_list[g][j < cnt ? j : cnt - 1];
            p = g_xf + (size_t)t * HDIM;
        } else {
            const int wnr = rr >> 5, within = rr & 31;
            const int irow = i0 + wnr * 16 + (within & 15);
            const __half* base = (within < 16) ? g_wgf : g_wuf;
            p = base + ((size_t)g * IDIM + irow) * HDIM;
        }
        srcs[i] = p + cc * 8;
        dsts[i] = sb + tile * TILE_SZ + rr * ROWB + cc * 16;
    }

    float acc[4][4][4];
#pragma unroll
    for (int mt = 0; mt < 4; mt++)
#pragma unroll
        for (int j = 0; j < 4; j++)
#pragma unroll
            for (int e = 0; e < 4; e++) acc[mt][j][e] = 0.f;

#pragma unroll
    for (int i = 0; i < 8; i++) cpasync16(dsts[i], srcs[i]);
    CP_COMMIT();
#pragma unroll
    for (int i = 0; i < 8; i++) cpasync16(dsts[i] + STAGE_SZ, srcs[i] + KC);
    CP_COMMIT();

    for (int c = 0; c < NC1; c++) {
        CP_WAIT(1);
        __syncthreads();
        mma_stage(sb + (uint32_t)((c % NSTAGE) * STAGE_SZ), wm, wn, lane, acc);
        if (c + 2 < NC1) {
            const int k0 = (c + 2) * KC;
            const uint32_t so = (uint32_t)(((c + 2) % NSTAGE) * STAGE_SZ);
#pragma unroll
            for (int i = 0; i < 8; i++) cpasync16(dsts[i] + so, srcs[i] + k0);
        }
        CP_COMMIT();
    }

    __syncthreads();
    float* sPg = (float*)smem;
    float* sPu = sPg + 512;
    float* sSf = sPu + 512;
    float* sSc = sSf + 1024;
    if (tid < 128) {
        ((float4*)sPg)[tid] = ((const float4*)(g_Pg + ((size_t)g * IDIM + i0) * GSZ))[tid];
        ((float4*)sPu)[tid] = ((const float4*)(g_Pu + ((size_t)g * IDIM + i0) * GSZ))[tid];
    }
    {
        const int rrow = tid >> 1, hf = tid & 1;
        const int j = n0 + rrow;
        const int t = g_list[g][j < cnt ? j : cnt - 1];
        ((float4*)sSf)[tid] =
            *(const float4*)(g_soft + ((size_t)t * NGRP + g) * GSZ + hf * 4);
        if (hf == 0) sSc[rrow] = g_scalar[(size_t)t * NGRP + g];
    }
    __syncthreads();

    const int r = lane >> 2, cb = (lane & 3) * 2;
#pragma unroll
    for (int mt = 0; mt < 4; mt++) {
#pragma unroll
        for (int e2 = 0; e2 < 2; e2++) {
            const int trow = wm * 64 + mt * 16 + r + e2 * 8;
            if (n0 + trow >= cnt) continue;
            float sf[8];
#pragma unroll
            for (int s = 0; s < 8; s++) sf[s] = sSf[trow * 8 + s];
            const float scl = sSc[trow];
            __half* pa = g_actf + ((size_t)g * N_TOK + n0 + trow) * IDIM + i0;
#pragma unroll
            for (int nt = 0; nt < 2; nt++) {
                float v0 = 0.f, v1 = 0.f;
#pragma unroll
                for (int p = 0; p < 2; p++) {
                    const int il = wn * 16 + nt * 8 + cb + p;
                    float gv = acc[mt][nt][e2 * 2 + p];
                    float uv = acc[mt][nt + 2][e2 * 2 + p];
#pragma unroll
                    for (int s = 0; s < 8; s++) {
                        gv += sf[s] * sPg[il * 8 + s];
                        uv += sf[s] * sPu[il * 8 + s];
                    }
                    const float sig = 1.f / (1.f + expf(-gv));
                    const float a = scl * (gv * sig * uv);
                    if (p == 0) v0 = a; else v1 = a;
                }
                __half2 hv = __floats2half2_rn(v0, v1);
                *(__half2*)(pa + wn * 16 + nt * 8 + cb) = hv;
            }
        }
    }
}

// ---------------------------------------------------------------------------
// G2 (per-group, compacted): y[t, h0..+128] += act_c[g] @ Wd_g^T, atomicAdd.
// ---------------------------------------------------------------------------
__global__ __launch_bounds__(256, 2) void moe_g2_mma(float* __restrict__ y)
{
    extern __shared__ char smem[];
    const uint32_t sb = s2u(smem);
    const int tid = threadIdx.x, lane = tid & 31;
    const int wn = (tid >> 5) & 3, wm = tid >> 7;
    const int g = blockIdx.z, n0 = blockIdx.x * 128, h0 = blockIdx.y * 128;

    const int cnt = g_cnt[g];
    if (n0 >= cnt) return;

    const __half* srcs[8];
    uint32_t dsts[8];
#pragma unroll
    for (int i = 0; i < 8; i++) {
        const int id = tid + i * 256;
        const int tile = id >> 10, rr = (id >> 3) & 127, cc = id & 7;
        const __half* p;
        if (tile == 0) {
            const int j = n0 + rr;
            const int jc = j < cnt ? j : cnt - 1;
            p = g_actf + ((size_t)g * N_TOK + jc) * IDIM;
        } else {
            p = g_wdf + ((size_t)g * HDIM + h0 + rr) * IDIM;
        }
        srcs[i] = p + cc * 8;
        dsts[i] = sb + tile * TILE_SZ + rr * ROWB + cc * 16;
    }

    float acc[4][4][4];
#pragma unroll
    for (int mt = 0; mt < 4; mt++)
#pragma unroll
        for (int j = 0; j < 4; j++)
#pragma unroll
            for (int e = 0; e < 4; e++) acc[mt][j][e] = 0.f;

#pragma unroll
    for (int i = 0; i < 8; i++) cpasync16(dsts[i], srcs[i]);
    CP_COMMIT();
#pragma unroll
    for (int i = 0; i < 8; i++) cpasync16(dsts[i] + STAGE_SZ, srcs[i] + KC);
    CP_COMMIT();

    for (int c = 0; c < NC2; c++) {
        CP_WAIT(1);
        __syncthreads();
        mma_stage(sb + (uint32_t)((c % NSTAGE) * STAGE_SZ), wm, wn, lane, acc);
        if (c + 2 < NC2) {
            const int k0 = (c + 2) * KC;
            const uint32_t so = (uint32_t)(((c + 2) % NSTAGE) * STAGE_SZ);
#pragma unroll
            for (int i = 0; i < 8; i++) cpasync16(dsts[i] + so, srcs[i] + k0);
        }
        CP_COMMIT();
    }

    const int r = lane >> 2, cb = (lane & 3) * 2;
#pragma unroll
    for (int mt = 0; mt < 4; mt++) {
#pragma unroll
        for (int e2 = 0; e2 < 2; e2++) {
            const int row = wm * 64 + mt * 16 + r + e2 * 8;
            if (n0 + row >= cnt) continue;
            const int t = g_list[g][n0 + row];
            float* yrow = y + (size_t)t * HDIM + h0 + wn * 32;
#pragma unroll
            for (int nt = 0; nt < 4; nt++) {
                atomicAdd(yrow + nt * 8 + cb,     acc[mt][nt][e2 * 2]);
                atomicAdd(yrow + nt * 8 + cb + 1, acc[mt][nt][e2 * 2 + 1]);
            }
        }
    }
}

// ---------------------------------------------------------------------------
// Launch
// ---------------------------------------------------------------------------
extern "C" void kernel_launch(void* const* d_in, const int* in_sizes, int n_in,
                              void* d_out, int out_size)
{
    const float* x      = (const float*)d_in[0];
    const float* gate_w = (const float*)d_in[1];
    const float* mask_w = (const float*)d_in[2];
    const float* Wg     = (const float*)d_in[3];
    const float* Wu     = (const float*)d_in[4];
    const float* Wd     = (const float*)d_in[5];
    const void*  invmap = (const void*)d_in[6];
    float* y = (float*)d_out;
    (void)in_sizes; (void)n_in;

    cudaFuncSetAttribute(moe_g1_mma, cudaFuncAttributeMaxDynamicSharedMemorySize, SMEM_TOTAL);
    cudaFuncSetAttribute(moe_g2_mma, cudaFuncAttributeMaxDynamicSharedMemorySize, SMEM_TOTAL);
    cudaFuncSetAttribute(moe_route,  cudaFuncAttributeMaxDynamicSharedMemorySize, RT_SMEM);
    cudaFuncSetAttribute(moe_pproj,  cudaFuncAttributeMaxDynamicSharedMemorySize, PP_SMEM);

    __half* wdf;
    cudaGetSymbolAddress((void**)&wdf, g_wdf);

    // zero y (G2 scatter-adds)
    cudaMemsetAsync(y, 0, (size_t)out_size * sizeof(float));

    // Wd -> fp16 (only standalone conversion left)
    to_half<<<2048, 256>>>((const float4*)Wd, (uint2*)wdf,
                           (int)((size_t)NGRP * HDIM * IDIM / 4));

    // routing (+ x->fp16) -> compaction ; P projections (+ Wg/Wu->fp16)
    moe_route<<<N_TOK / RT_TOK, 256, RT_SMEM>>>(x, gate_w, invmap);
    moe_compact<<<NGRP, 256>>>();
    moe_pproj<<<(NGRP * IDIM) / 8, 256, PP_SMEM>>>(Wg, Wu, mask_w);

    // G1: compacted gate/up GEMM + fused epilogue
    dim3 g1grid(N_TOK / 128, IDIM / 64, NGRP);
    moe_g1_mma<<<g1grid, 256, SMEM_TOTAL>>>();

    // G2: per-group down-proj, scatter-add into y
    dim3 g2grid(N_TOK / 128, HDIM / 128, NGRP);
    moe_g2_mma<<<g2grid, 256, SMEM_TOTAL>>>(y);
}

// round 17
// speedup vs baseline: 1.0047x; 1.0047x over previous
#include <cuda_runtime.h>
#include <cuda_bf16.h>
#include <cuda_fp16.h>
#include <math.h>
#include <stdint.h>

// Problem constants
#define N_TOK 2048
#define HDIM  2048
#define IDIM  1408
#define NEXP  64
#define NGRP  8
#define GSZ   8
#define TOPK  8

// GEMM tiling (fp16 operands in smem)
#define KC      64
#define ROWB    144
#define TILE_SZ (128*ROWB)
#define STAGE_SZ (2*TILE_SZ)
#define NSTAGE  3
#define SMEM_TOTAL (NSTAGE*STAGE_SZ)  // 110592 B
#define NC1 (HDIM/KC)                 // 32
#define NC2 (IDIM/KC)                 // 22

#define RT_TOK 8
#define RT_SMEM (RT_TOK*HDIM*4)       // 65536 B dynamic smem for route
#define PP_SMEM (HDIM*9*4)            // 73728 B dynamic smem for pproj (stride-9 M)

// ---------------------------------------------------------------------------
// Device global scratch
// ---------------------------------------------------------------------------
__device__ float g_soft[(size_t)N_TOK * NGRP * GSZ];
__device__ float g_scalar[(size_t)N_TOK * NGRP];
__device__ float g_Pg[(size_t)NGRP * IDIM * GSZ];
__device__ float g_Pu[(size_t)NGRP * IDIM * GSZ];

__device__ int g_list[NGRP][N_TOK];
__device__ int g_cnt[NGRP];

__device__ __half g_xf[(size_t)N_TOK * HDIM];
__device__ __half g_wgf[(size_t)NGRP * IDIM * HDIM];
__device__ __half g_wuf[(size_t)NGRP * IDIM * HDIM];
__device__ __half g_wdf[(size_t)NGRP * HDIM * IDIM];
__device__ __half g_actf[(size_t)NGRP * N_TOK * IDIM];

// ---------------------------------------------------------------------------
// PTX helpers (sm_80-portable only)
// ---------------------------------------------------------------------------
__device__ __forceinline__ uint32_t s2u(const void* p) {
    uint32_t a;
    asm("{ .reg .u64 t; cvta.to.shared.u64 t, %1; cvt.u32.u64 %0, t; }"
        : "=r"(a) : "l"(p));
    return a;
}
__device__ __forceinline__ void cpasync16(uint32_t s, const void* g) {
    asm volatile("cp.async.cg.shared.global [%0], [%1], 16;"
                 :: "r"(s), "l"(g) : "memory");
}
#define CP_COMMIT() asm volatile("cp.async.commit_group;" ::: "memory")
#define CP_WAIT(n)  asm volatile("cp.async.wait_group %0;" :: "n"(n) : "memory")

__device__ __forceinline__ void ldsm4(uint32_t* r, uint32_t addr) {
    asm volatile("ldmatrix.sync.aligned.m8n8.x4.shared.b16 {%0,%1,%2,%3}, [%4];"
                 : "=r"(r[0]), "=r"(r[1]), "=r"(r[2]), "=r"(r[3]) : "r"(addr));
}
__device__ __forceinline__ void mma16816(float* d, const uint32_t* a,
                                         uint32_t b0, uint32_t b1) {
    asm volatile(
        "mma.sync.aligned.m16n8k16.row.col.f32.f16.f16.f32 "
        "{%0,%1,%2,%3}, {%4,%5,%6,%7}, {%8,%9}, {%0,%1,%2,%3};"
        : "+f"(d[0]), "+f"(d[1]), "+f"(d[2]), "+f"(d[3])
        : "r"(a[0]), "r"(a[1]), "r"(a[2]), "r"(a[3]), "r"(b0), "r"(b1));
}

// ---------------------------------------------------------------------------
// Prep: fp32 -> fp16 (only Wd)
// ---------------------------------------------------------------------------
__global__ __launch_bounds__(256) void to_half(
    const float4* __restrict__ src, uint2* __restrict__ dst, int n4)
{
    for (int i = blockIdx.x * 256 + threadIdx.x; i < n4; i += gridDim.x * 256) {
        float4 v = src[i];
        __half2 a = __floats2half2_rn(v.x, v.y);
        __half2 b = __floats2half2_rn(v.z, v.w);
        uint2 o;
        o.x = *(uint32_t*)&a;
        o.y = *(uint32_t*)&b;
        dst[i] = o;
    }
}

// ---------------------------------------------------------------------------
// Routing: 8 tokens/block (gate_w reuse x8), fused x->fp16,
// warp-per-token softmax/top-8 (lower-index tie-break = first-wins).
// ---------------------------------------------------------------------------
__global__ __launch_bounds__(256) void moe_route(
    const float* __restrict__ x, const float* __restrict__ gate_w,
    const void* __restrict__ inv_map_raw)
{
    extern __shared__ float xs[];            // RT_TOK * HDIM
    __shared__ float sc[RT_TOK][NEXP];

    const int tid = threadIdx.x;
    const int n0 = blockIdx.x * RT_TOK;
    const int warp = tid >> 5, lane = tid & 31;

    for (int u = tid; u < RT_TOK * HDIM / 4; u += 256) {
        const int row = u >> 9;
        const int c4 = u & 511;
        float4 v = ((const float4*)(x + (size_t)(n0 + row) * HDIM))[c4];
        ((float4*)(xs + row * HDIM))[c4] = v;
        __half2 h0 = __floats2half2_rn(v.x, v.y);
        __half2 h1 = __floats2half2_rn(v.z, v.w);
        uint2 o; o.x = *(uint32_t*)&h0; o.y = *(uint32_t*)&h1;
        ((uint2*)(g_xf + (size_t)(n0 + row) * HDIM))[c4] = o;
    }
    __syncthreads();

    float acc[RT_TOK][8];
#pragma unroll
    for (int t = 0; t < RT_TOK; t++)
#pragma unroll
        for (int j = 0; j < 8; j++) acc[t][j] = 0.f;

    const float* gw = gate_w + (size_t)(warp * 8) * HDIM;
    for (int h = lane; h < HDIM; h += 32) {
        float gv[8];
#pragma unroll
        for (int j = 0; j < 8; j++) gv[j] = gw[(size_t)j * HDIM + h];
#pragma unroll
        for (int t = 0; t < RT_TOK; t++) {
            const float xv = xs[t * HDIM + h];
#pragma unroll
            for (int j = 0; j < 8; j++) acc[t][j] += xv * gv[j];
        }
    }
#pragma unroll
    for (int t = 0; t < RT_TOK; t++)
#pragma unroll
        for (int j = 0; j < 8; j++) {
            float v = acc[t][j];
#pragma unroll
            for (int o = 16; o > 0; o >>= 1)
                v += __shfl_down_sync(0xffffffffu, v, o);
            if (lane == 0) sc[t][warp * 8 + j] = v;
        }
    __syncthreads();

    {
        const int t = warp;
        const int n = n0 + t;
        float v0 = sc[t][lane], v1 = sc[t][lane + 32];

        float m = fmaxf(v0, v1);
#pragma unroll
        for (int o = 16; o > 0; o >>= 1)
            m = fmaxf(m, __shfl_xor_sync(0xffffffffu, m, o));
        float e0 = expf(v0 - m), e1 = expf(v1 - m);
        float s = e0 + e1;
#pragma unroll
        for (int o = 16; o > 0; o >>= 1)
            s += __shfl_xor_sync(0xffffffffu, s, o);
        const float inv = 1.f / s;
        float a0 = e0 * inv, a1 = e1 * inv;

        float win_val[TOPK]; int win_idx[TOPK];
#pragma unroll
        for (int k = 0; k < TOPK; k++) {
            float bv; int bi;
            if (a0 >= a1) { bv = a0; bi = lane; } else { bv = a1; bi = lane + 32; }
#pragma unroll
            for (int o = 16; o > 0; o >>= 1) {
                float ov = __shfl_xor_sync(0xffffffffu, bv, o);
                int   oi = __shfl_xor_sync(0xffffffffu, bi, o);
                if (ov > bv || (ov == bv && oi < bi)) { bv = ov; bi = oi; }
            }
            win_val[k] = bv; win_idx[k] = bi;
            if (bi == lane)      a0 = -1.f;
            if (bi == lane + 32) a1 = -1.f;
        }

        if (lane < NGRP) {
            const int g = lane;
            const int* im32 = (const int*)inv_map_raw;
            const bool is64 = (im32[1] == 0);
            const long long* im64 = (const long long*)inv_map_raw;
            float f[GSZ]; float ss = 0.f;
#pragma unroll
            for (int sl = 0; sl < GSZ; sl++) {
                const int slot = g * GSZ + sl;
                const int e = is64 ? (int)im64[slot] : im32[slot];
                float w = 0.f;
#pragma unroll
                for (int k = 0; k < TOPK; k++)
                    if (win_idx[k] == e) w = win_val[k];
                f[sl] = w; ss += w;
            }
            g_scalar[(size_t)n * NGRP + g] = ss;
            float mx = -1e30f;
#pragma unroll
            for (int sl = 0; sl < GSZ; sl++) {
                float v = (f[sl] == 0.f) ? -1e9f : f[sl];
                f[sl] = v; mx = fmaxf(mx, v);
            }
            float es = 0.f;
#pragma unroll
            for (int sl = 0; sl < GSZ; sl++) { float v = expf(f[sl] - mx); f[sl] = v; es += v; }
            const float iv = 1.f / es;
#pragma unroll
            for (int sl = 0; sl < GSZ; sl++)
                g_soft[((size_t)n * NGRP + g) * GSZ + sl] = f[sl] * iv;
        }
    }
}

// ---------------------------------------------------------------------------
// Compaction
// ---------------------------------------------------------------------------
__global__ __launch_bounds__(256) void moe_compact()
{
    const int g = blockIdx.x, tid = threadIdx.x;
    __shared__ int warpsum[8];

    int flags[8]; int local = 0;
#pragma unroll
    for (int j = 0; j < 8; j++) {
        const int t = tid * 8 + j;
        flags[j] = (g_scalar[(size_t)t * NGRP + g] != 0.f) ? 1 : 0;
        local += flags[j];
    }
    int v = local;
#pragma unroll
    for (int o = 1; o < 32; o <<= 1) {
        int nv = __shfl_up_sync(0xffffffffu, v, o);
        if ((tid & 31) >= o) v += nv;
    }
    if ((tid & 31) == 31) warpsum[tid >> 5] = v;
    __syncthreads();
    if (tid < 8) {
        int w = warpsum[tid];
#pragma unroll
        for (int o = 1; o < 8; o <<= 1) {
            int nw = __shfl_up_sync(0xffu, w, o);
            if (tid >= o) w += nw;
        }
        warpsum[tid] = w;
    }
    __syncthreads();
    int base = v - local + ((tid >= 32) ? warpsum[(tid >> 5) - 1] : 0);
#pragma unroll
    for (int j = 0; j < 8; j++) {
        if (flags[j]) g_list[g][base++] = tid * 8 + j;
    }
    if (tid == 255) g_cnt[g] = base;
}

// ---------------------------------------------------------------------------
// P projections (fp32 exact): M_g staged in smem (stride 9, conflict-free),
// fused Wg/Wu -> fp16. One block = 8 rows (i) of ONE group (IDIM/8=176 | grid).
// ---------------------------------------------------------------------------
__global__ __launch_bounds__(256) void moe_pproj(
    const float* __restrict__ Wg, const float* __restrict__ Wu,
    const float* __restrict__ M)
{
    extern __shared__ float ms[];            // HDIM rows x stride 9
    const int tid = threadIdx.x;
    const int b = blockIdx.x;
    const int g = b / (IDIM / 8);
    const int i0 = (b % (IDIM / 8)) * 8;
    const int warp = tid >> 5, lane = tid & 31;

    // stage M_g: HDIM x 8 floats -> stride-9 smem rows
    {
        const float4* m4 = (const float4*)(M + (size_t)g * HDIM * GSZ);
        for (int u = tid; u < HDIM * 2; u += 256) {
            const int row = u >> 1, hf = u & 1;
            float4 v = m4[u];
            float* d = ms + row * 9 + hf * 4;
            d[0] = v.x; d[1] = v.y; d[2] = v.z; d[3] = v.w;
        }
    }
    __syncthreads();

    const int i = i0 + warp;
    const size_t rowoff = ((size_t)g * IDIM + i) * HDIM;
    const float* wgr = Wg + rowoff;
    const float* wur = Wu + rowoff;
    __half* wgo = g_wgf + rowoff;
    __half* wuo = g_wuf + rowoff;

    float ag[8], au[8];
#pragma unroll
    for (int s = 0; s < 8; s++) { ag[s] = 0.f; au[s] = 0.f; }

    for (int h = lane; h < HDIM; h += 32) {
        const float wgv = wgr[h];
        const float wuv = wur[h];
        wgo[h] = __float2half_rn(wgv);
        wuo[h] = __float2half_rn(wuv);
        const float* mr = ms + h * 9;        // stride 9 -> conflict-free
#pragma unroll
        for (int s = 0; s < 8; s++) {
            ag[s] += wgv * mr[s];
            au[s] += wuv * mr[s];
        }
    }
#pragma unroll
    for (int s = 0; s < 8; s++) {
#pragma unroll
        for (int o = 16; o > 0; o >>= 1) {
            ag[s] += __shfl_down_sync(0xffffffffu, ag[s], o);
            au[s] += __shfl_down_sync(0xffffffffu, au[s], o);
        }
    }
    if (lane == 0) {
        float* pg = &g_Pg[((size_t)g * IDIM + i) * GSZ];
        float* pu = &g_Pu[((size_t)g * IDIM + i) * GSZ];
#pragma unroll
        for (int s = 0; s < 8; s++) { pg[s] = ag[s]; pu[s] = au[s]; }
    }
}

// ---------------------------------------------------------------------------
// fp16 warp-MMA stage: warp tile 64(m) x 32(n), KC=64.
// ---------------------------------------------------------------------------
__device__ __forceinline__ void mma_stage(uint32_t sbuf, int wm, int wn, int lane,
                                          float acc[4][4][4]) {
    const uint32_t lm = (uint32_t)((lane & 15) * ROWB + (lane >> 4) * 16);
#pragma unroll
    for (int s = 0; s < 4; s++) {
        const uint32_t base = sbuf + lm + s * 32;
        uint32_t a[4][4], bx[2][4];
#pragma unroll
        for (int mt = 0; mt < 4; mt++)
            ldsm4(a[mt], base + (wm * 64 + mt * 16) * ROWB);
#pragma unroll
        for (int bt = 0; bt < 2; bt++)
            ldsm4(bx[bt], base + TILE_SZ + (wn * 32 + bt * 16) * ROWB);
#pragma unroll
        for (int mt = 0; mt < 4; mt++)
#pragma unroll
            for (int j = 0; j < 4; j++)
                mma16816(acc[mt][j], a[mt],
                         bx[j >> 1][j & 1], bx[j >> 1][2 + (j & 1)]);
    }
}

// ---------------------------------------------------------------------------
// G1 (compacted): act_c[g, pos0..+128, i0..+64]; 3-stage ring, 1 sync/chunk.
// ---------------------------------------------------------------------------
__global__ __launch_bounds__(256, 2) void moe_g1_mma()
{
    extern __shared__ char smem[];
    const uint32_t sb = s2u(smem);
    const int tid = threadIdx.x, lane = tid & 31;
    const int wn = (tid >> 5) & 3, wm = tid >> 7;
    const int g = blockIdx.z, i0 = blockIdx.y * 64, n0 = blockIdx.x * 128;

    const int cnt = g_cnt[g];
    if (n0 >= cnt) return;

    const __half* srcs[8];
    uint32_t dsts[8];
#pragma unroll
    for (int i = 0; i < 8; i++) {
        const int id = tid + i * 256;
        const int tile = id >> 10, rr = (id >> 3) & 127, cc = id & 7;
        const __half* p;
        if (tile == 0) {
            const int j = n0 + rr;
            const int t = g_list[g][j < cnt ? j : cnt - 1];
            p = g_xf + (size_t)t * HDIM;
        } else {
            const int wnr = rr >> 5, within = rr & 31;
            const int irow = i0 + wnr * 16 + (within & 15);
            const __half* base = (within < 16) ? g_wgf : g_wuf;
            p = base + ((size_t)g * IDIM + irow) * HDIM;
        }
        srcs[i] = p + cc * 8;
        dsts[i] = sb + tile * TILE_SZ + rr * ROWB + cc * 16;
    }

    float acc[4][4][4];
#pragma unroll
    for (int mt = 0; mt < 4; mt++)
#pragma unroll
        for (int j = 0; j < 4; j++)
#pragma unroll
            for (int e = 0; e < 4; e++) acc[mt][j][e] = 0.f;

#pragma unroll
    for (int i = 0; i < 8; i++) cpasync16(dsts[i], srcs[i]);
    CP_COMMIT();
#pragma unroll
    for (int i = 0; i < 8; i++) cpasync16(dsts[i] + STAGE_SZ, srcs[i] + KC);
    CP_COMMIT();

    for (int c = 0; c < NC1; c++) {
        CP_WAIT(1);
        __syncthreads();
        mma_stage(sb + (uint32_t)((c % NSTAGE) * STAGE_SZ), wm, wn, lane, acc);
        if (c + 2 < NC1) {
            const int k0 = (c + 2) * KC;
            const uint32_t so = (uint32_t)(((c + 2) % NSTAGE) * STAGE_SZ);
#pragma unroll
            for (int i = 0; i < 8; i++) cpasync16(dsts[i] + so, srcs[i] + k0);
        }
        CP_COMMIT();
    }

    __syncthreads();
    float* sPg = (float*)smem;
    float* sPu = sPg + 512;
    float* sSf = sPu + 512;
    float* sSc = sSf + 1024;
    if (tid < 128) {
        ((float4*)sPg)[tid] = ((const float4*)(g_Pg + ((size_t)g * IDIM + i0) * GSZ))[tid];
        ((float4*)sPu)[tid] = ((const float4*)(g_Pu + ((size_t)g * IDIM + i0) * GSZ))[tid];
    }
    {
        const int rrow = tid >> 1, hf = tid & 1;
        const int j = n0 + rrow;
        const int t = g_list[g][j < cnt ? j : cnt - 1];
        ((float4*)sSf)[tid] =
            *(const float4*)(g_soft + ((size_t)t * NGRP + g) * GSZ + hf * 4);
        if (hf == 0) sSc[rrow] = g_scalar[(size_t)t * NGRP + g];
    }
    __syncthreads();

    const int r = lane >> 2, cb = (lane & 3) * 2;
#pragma unroll
    for (int mt = 0; mt < 4; mt++) {
#pragma unroll
        for (int e2 = 0; e2 < 2; e2++) {
            const int trow = wm * 64 + mt * 16 + r + e2 * 8;
            if (n0 + trow >= cnt) continue;
            float sf[8];
#pragma unroll
            for (int s = 0; s < 8; s++) sf[s] = sSf[trow * 8 + s];
            const float scl = sSc[trow];
            __half* pa = g_actf + ((size_t)g * N_TOK + n0 + trow) * IDIM + i0;
#pragma unroll
            for (int nt = 0; nt < 2; nt++) {
                float v0 = 0.f, v1 = 0.f;
#pragma unroll
                for (int p = 0; p < 2; p++) {
                    const int il = wn * 16 + nt * 8 + cb + p;
                    float gv = acc[mt][nt][e2 * 2 + p];
                    float uv = acc[mt][nt + 2][e2 * 2 + p];
#pragma unroll
                    for (int s = 0; s < 8; s++) {
                        gv += sf[s] * sPg[il * 8 + s];
                        uv += sf[s] * sPu[il * 8 + s];
                    }
                    const float sig = 1.f / (1.f + expf(-gv));
                    const float a = scl * (gv * sig * uv);
                    if (p == 0) v0 = a; else v1 = a;
                }
                __half2 hv = __floats2half2_rn(v0, v1);
                *(__half2*)(pa + wn * 16 + nt * 8 + cb) = hv;
            }
        }
    }
}

// ---------------------------------------------------------------------------
// G2 (per-group, compacted): y[t, h0..+128] += act_c[g] @ Wd_g^T, atomicAdd.
// ---------------------------------------------------------------------------
__global__ __launch_bounds__(256, 2) void moe_g2_mma(float* __restrict__ y)
{
    extern __shared__ char smem[];
    const uint32_t sb = s2u(smem);
    const int tid = threadIdx.x, lane = tid & 31;
    const int wn = (tid >> 5) & 3, wm = tid >> 7;
    const int g = blockIdx.z, n0 = blockIdx.x * 128, h0 = blockIdx.y * 128;

    const int cnt = g_cnt[g];
    if (n0 >= cnt) return;

    const __half* srcs[8];
    uint32_t dsts[8];
#pragma unroll
    for (int i = 0; i < 8; i++) {
        const int id = tid + i * 256;
        const int tile = id >> 10, rr = (id >> 3) & 127, cc = id & 7;
        const __half* p;
        if (tile == 0) {
            const int j = n0 + rr;
            const int jc = j < cnt ? j : cnt - 1;
            p = g_actf + ((size_t)g * N_TOK + jc) * IDIM;
        } else {
            p = g_wdf + ((size_t)g * HDIM + h0 + rr) * IDIM;
        }
        srcs[i] = p + cc * 8;
        dsts[i] = sb + tile * TILE_SZ + rr * ROWB + cc * 16;
    }

    float acc[4][4][4];
#pragma unroll
    for (int mt = 0; mt < 4; mt++)
#pragma unroll
        for (int j = 0; j < 4; j++)
#pragma unroll
            for (int e = 0; e < 4; e++) acc[mt][j][e] = 0.f;

#pragma unroll
    for (int i = 0; i < 8; i++) cpasync16(dsts[i], srcs[i]);
    CP_COMMIT();
#pragma unroll
    for (int i = 0; i < 8; i++) cpasync16(dsts[i] + STAGE_SZ, srcs[i] + KC);
    CP_COMMIT();

    for (int c = 0; c < NC2; c++) {
        CP_WAIT(1);
        __syncthreads();
        mma_stage(sb + (uint32_t)((c % NSTAGE) * STAGE_SZ), wm, wn, lane, acc);
        if (c + 2 < NC2) {
            const int k0 = (c + 2) * KC;
            const uint32_t so = (uint32_t)(((c + 2) % NSTAGE) * STAGE_SZ);
#pragma unroll
            for (int i = 0; i < 8; i++) cpasync16(dsts[i] + so, srcs[i] + k0);
        }
        CP_COMMIT();
    }

    const int r = lane >> 2, cb = (lane & 3) * 2;
#pragma unroll
    for (int mt = 0; mt < 4; mt++) {
#pragma unroll
        for (int e2 = 0; e2 < 2; e2++) {
            const int row = wm * 64 + mt * 16 + r + e2 * 8;
            if (n0 + row >= cnt) continue;
            const int t = g_list[g][n0 + row];
            float* yrow = y + (size_t)t * HDIM + h0 + wn * 32;
#pragma unroll
            for (int nt = 0; nt < 4; nt++) {
                atomicAdd(yrow + nt * 8 + cb,     acc[mt][nt][e2 * 2]);
                atomicAdd(yrow + nt * 8 + cb + 1, acc[mt][nt][e2 * 2 + 1]);
            }
        }
    }
}

// ---------------------------------------------------------------------------
// Launch
// ---------------------------------------------------------------------------
extern "C" void kernel_launch(void* const* d_in, const int* in_sizes, int n_in,
                              void* d_out, int out_size)
{
    const float* x      = (const float*)d_in[0];
    const float* gate_w = (const float*)d_in[1];
    const float* mask_w = (const float*)d_in[2];
    const float* Wg     = (const float*)d_in[3];
    const float* Wu     = (const float*)d_in[4];
    const float* Wd     = (const float*)d_in[5];
    const void*  invmap = (const void*)d_in[6];
    float* y = (float*)d_out;
    (void)in_sizes; (void)n_in;

    cudaFuncSetAttribute(moe_g1_mma, cudaFuncAttributeMaxDynamicSharedMemorySize, SMEM_TOTAL);
    cudaFuncSetAttribute(moe_g2_mma, cudaFuncAttributeMaxDynamicSharedMemorySize, SMEM_TOTAL);
    cudaFuncSetAttribute(moe_route,  cudaFuncAttributeMaxDynamicSharedMemorySize, RT_SMEM);
    cudaFuncSetAttribute(moe_pproj,  cudaFuncAttributeMaxDynamicSharedMemorySize, PP_SMEM);

    __half* wdf;
    cudaGetSymbolAddress((void**)&wdf, g_wdf);

    // zero y (G2 scatter-adds)
    cudaMemsetAsync(y, 0, (size_t)out_size * sizeof(float));

    // Wd -> fp16 (only standalone conversion left)
    to_half<<<2048, 256>>>((const float4*)Wd, (uint2*)wdf,
                           (int)((size_t)NGRP * HDIM * IDIM / 4));

    // routing (+ x->fp16) -> compaction ; P projections (+ Wg/Wu->fp16)
    moe_route<<<N_TOK / RT_TOK, 256, RT_SMEM>>>(x, gate_w, invmap);
    moe_compact<<<NGRP, 256>>>();
    moe_pproj<<<(NGRP * IDIM) / 8, 256, PP_SMEM>>>(Wg, Wu, mask_w);

    // G1: compacted gate/up GEMM + fused epilogue
    dim3 g1grid(N_TOK / 128, IDIM / 64, NGRP);
    moe_g1_mma<<<g1grid, 256, SMEM_TOTAL>>>();

    // G2: per-group down-proj, scatter-add into y
    dim3 g2grid(N_TOK / 128, HDIM / 128, NGRP);
    moe_g2_mma<<<g2grid, 256, SMEM_TOTAL>>>(y);
}